// round 4
// baseline (speedup 1.0000x reference)
#include <cuda_runtime.h>

// CTC batch cost, forward (alpha) recursion only.
// B=128, T=512, C=1024, L=48 -> S=2L+1=97 states, blank = C-1 = 1023.
//
// One block per batch element; thread s owns CTC state s (s < 97; extra
// threads are benign dummies that gather the blank column so the block stays
// convergent). Alpha recursion over T with a double-buffered shared array
// (one __syncthreads per timestep), a depth-8 register prefetch ring on the
// gathered y_pred values (hides DRAM/L2 latency), and a 1-step-ahead
// log-prob pipeline so the MUFU LG2 for lp overlaps the barrier wait instead
// of sitting on the per-step critical chain.
//
// NOTE: y_true is int32 (JAX x64 disabled => .astype(jnp.int64) materializes
// int32 — reading it as int64 was the R1 OOB crash).

#define B_ 128
#define T_ 512
#define C_ 1024
#define L_ 48
#define S_ 97
#define BLANK_ (C_ - 1)
#define EPS_ 1e-7f
#define NEG_ (-1e30f)
#define PD_ 8  // prefetch depth (raw global loads, in timesteps)

__global__ __launch_bounds__(128, 1)
void ctc_loss_kernel(const float* __restrict__ y_pred,
                     const int* __restrict__ y_true,
                     float* __restrict__ out)
{
    // Padded so every thread (s up to 127) may write sh[.][s+2] without
    // bounds checks; only indices [0, S_+1] are ever read.
    __shared__ float sh[2][136];

    const int b = blockIdx.x;
    const int s = threadIdx.x;

    // left padding = alpha[s-1], alpha[s-2] for s=0/1
    if (s < 2) { sh[0][s] = NEG_; sh[1][s] = NEG_; }

    // ---- resolve this state's class index and skip flag (once) ----
    int cls = BLANK_;
    bool skip = false;
    if (s & 1) {
        int k = s >> 1;                 // label position, valid for s < S_
        if (k > L_ - 1) k = L_ - 1;     // clamp dummy threads into range
        cls = y_true[b * L_ + k];
        // skip allowed iff ext[s] != blank (always true for odd s: labels
        // exclude blank) and ext[s] != ext[s-2] (prev label); s==1 always
        // allowed (ext_m2 = -1 sentinel in the reference).
        skip = (k == 0) ? true : (cls != y_true[b * L_ + k - 1]);
    }

    // column walker: y_pred[b, t, cls], stride C_ floats per t
    const float* q = y_pred + (size_t)b * T_ * C_ + cls;

    // ---- t = 0 init ----
    float alpha;
    {
        float lp0 = __logf(q[0] + EPS_);
        alpha = (s <= 1) ? lp0 : NEG_;
    }

    // ---- prefetch ring: raw probs for t = 1..PD_ ----
    float pf[PD_];
#pragma unroll
    for (int k = 0; k < PD_; ++k) {
        int t = 1 + k;
        if (t > T_ - 1) t = T_ - 1;
        pf[k] = q[(size_t)t * C_];
    }

    // lp pipeline: log-prob for the upcoming step, computed one step early
    float lp_next = __logf(pf[0] + EPS_);

    // ---- alpha recursion, t = 1 .. T_-1 ----
    int cur = 0;
    for (int tb = 1; tb < T_; tb += PD_) {
#pragma unroll
        for (int u = 0; u < PD_; ++u) {
            const int t = tb + u;
            if (t >= T_) break;        // uniform across block: barriers match

            float lp = lp_next;

            // re-issue the global load PD_ steps ahead (clamped at tail)
            int tn = t + PD_;
            if (tn > T_ - 1) tn = T_ - 1;
            pf[u] = q[(size_t)tn * C_];

            sh[cur][s + 2] = alpha;
            __syncthreads();

            // convert NEXT step's raw prob while waiting on shared reads —
            // off the critical chain (joins only at next step's final add)
            float raw_n = pf[(u + 1) % PD_];
            lp_next = __logf(raw_n + EPS_);

            float a1 = sh[cur][s + 1];
            float a2 = sh[cur][s];

            // 3-way logaddexp (skip-gated third arm)
            float m = fmaxf(alpha, a1);
            if (skip) m = fmaxf(m, a2);
            float sum = __expf(alpha - m) + __expf(a1 - m);
            if (skip) sum += __expf(a2 - m);
            alpha = m + __logf(sum) + lp;

            cur ^= 1;   // double buffer: no second barrier needed
        }
    }

    // ---- loss = -logaddexp(alpha[S-1], alpha[S-2]) ----
    sh[cur][s + 2] = alpha;
    __syncthreads();
    if (s == 0) {
        float aN  = sh[cur][S_ + 1];   // state 96 (final blank)
        float aN1 = sh[cur][S_ + 0];   // state 95 (final label)
        float m = fmaxf(aN, aN1);
        out[b] = -(m + __logf(__expf(aN - m) + __expf(aN1 - m)));
    }
}

extern "C" void kernel_launch(void* const* d_in, const int* in_sizes, int n_in,
                              void* d_out, int out_size)
{
    const float* y_pred = (const float*)d_in[0];   // [B, T, C] f32
    const int*   y_true = (const int*)d_in[1];     // [B, L] int32
    float*       out    = (float*)d_out;           // [B, 1] f32

    ctc_loss_kernel<<<B_, 128>>>(y_pred, y_true, out);
}

// round 7
// speedup vs baseline: 1.0546x; 1.0546x over previous
#include <cuda_runtime.h>

// CTC batch cost — single-warp-per-batch, barrier-free formulation.
// B=128, T=512, C=1024, L=48 -> S=97 states, blank = 1023.
//
// Lane l owns 4 consecutive CTC states {4l,4l+1,4l+2,4l+3}. Even states are
// blanks (skip never applies), so the only cross-lane value needed per step
// is alpha[4l-1] = neighbor lane's A3 -> ONE __shfl_up_sync per timestep and
// no __syncthreads / shared memory at all (R4 profile: the 4-warp barrier +
// smem round-trip dominated the ~300 cyc/step).
//
// Alphas kept in log2 domain: EX2/LG2 MUFU ops directly, no ln2 multiplies
// on the chain; diff-form lse2 for blank states cuts EX2 count. Per-lane
// loads: 2 gathered label columns + 1 warp-broadcast blank column, depth-8
// register prefetch ring (DRAM ~577cyc << 8 * ~130cyc step).
//
// y_true is int32 (JAX x64 disabled).

#define B_ 128
#define T_ 512
#define C_ 1024
#define L_ 48
#define BLANK_ (C_ - 1)
#define EPS_ 1e-7f
#define NEG2_ (-1.442695e30f)   /* -1e30 / ln2 (log2 domain) */
#define LN2_ 0.6931471805599453f
#define PD_ 8

__device__ __forceinline__ float ex2(float x) {
    float r; asm("ex2.approx.ftz.f32 %0, %1;" : "=f"(r) : "f"(x)); return r;
}
__device__ __forceinline__ float lg2(float x) {
    float r; asm("lg2.approx.ftz.f32 %0, %1;" : "=f"(r) : "f"(x)); return r;
}

__global__ __launch_bounds__(32, 1)
void ctc_loss_kernel(const float* __restrict__ y_pred,
                     const int* __restrict__ y_true,
                     float* __restrict__ out)
{
    const int b = blockIdx.x;
    const int l = threadIdx.x;          // lane 0..31; lanes >24 are dummies

    // ---- per-lane label classes + skip flags (resolved once) ----
    // state 4l+1 -> label index 2l ; state 4l+3 -> label index 2l+1
    int k1 = 2 * l;      if (k1 > L_ - 1) k1 = L_ - 1;   // clamp dummies
    int k3 = 2 * l + 1;  if (k3 > L_ - 1) k3 = L_ - 1;
    const int* lab = y_true + b * L_;
    const int cls1 = lab[k1];
    const int cls3 = lab[k3];
    // skip for odd states: label != previous label (s==1: always allowed,
    // but its skip source alpha[-1] is NEG anyway -> set true, harmless)
    const bool skip1 = (l == 0) ? true : (cls1 != lab[k1 - 1]);
    const bool skip3 = (cls3 != cls1);

    // column walkers (stride C_ floats per timestep)
    const float* base = y_pred + (size_t)b * T_ * C_;
    const float* qb = base + BLANK_;   // same addr across warp -> broadcast
    const float* q1 = base + cls1;
    const float* q3 = base + cls3;

    // ---- t = 0 init (log2 domain) ----
    float A0, A1, A2 = NEG2_, A3 = NEG2_;
    {
        float lpb0 = lg2(qb[0] + EPS_);
        float lp10 = lg2(q1[0] + EPS_);
        A0 = (l == 0) ? lpb0 : NEG2_;   // state 0 (blank)
        A1 = (l == 0) ? lp10 : NEG2_;   // state 1 (label 0)
    }

    // ---- prefetch rings: raw probs for t = 1..PD_ ----
    float pfb[PD_], pf1[PD_], pf3[PD_];
#pragma unroll
    for (int k = 0; k < PD_; ++k) {
        int t = 1 + k; if (t > T_ - 1) t = T_ - 1;
        size_t off = (size_t)t * C_;
        pfb[k] = qb[off]; pf1[k] = q1[off]; pf3[k] = q3[off];
    }
    // one-step-ahead log2 conversions (off the critical chain)
    float lpb_n = lg2(pfb[0] + EPS_);
    float lp1_n = lg2(pf1[0] + EPS_);
    float lp3_n = lg2(pf3[0] + EPS_);

    // ---- recursion t = 1 .. T_-1 ----
    for (int tb = 1; tb < T_; tb += PD_) {
#pragma unroll
        for (int u = 0; u < PD_; ++u) {
            const int t = tb + u;
            if (t >= T_) break;         // warp-uniform

            const float lpb = lpb_n, lp1 = lp1_n, lp3 = lp3_n;

            // re-issue loads PD_ steps ahead (clamped redundant at tail)
            int tn = t + PD_; if (tn > T_ - 1) tn = T_ - 1;
            size_t off = (size_t)tn * C_;
            pfb[u] = qb[off]; pf1[u] = q1[off]; pf3[u] = q3[off];

            // neighbor value: alpha[4l-1] = lane (l-1) A3
            float n3 = __shfl_up_sync(0xffffffffu, A3, 1);
            if (l == 0) n3 = NEG2_;

            // convert NEXT step's raw probs while shfl is in flight
            const int un = (u + 1) % PD_;
            lpb_n = lg2(pfb[un] + EPS_);
            lp1_n = lg2(pf1[un] + EPS_);
            lp3_n = lg2(pf3[un] + EPS_);

            // state 4l   (blank): lse2(A0, n3), diff-form
            float m0 = fmaxf(A0, n3);
            float d0 = fabsf(A0 - n3);
            float A0n = m0 + lg2(1.0f + ex2(-d0)) + lpb;

            // state 4l+1 (label): lse3(A1, A0, skip1 ? n3)
            float m1 = fmaxf(A1, A0); if (skip1) m1 = fmaxf(m1, n3);
            float s1 = ex2(A1 - m1) + ex2(A0 - m1);
            if (skip1) s1 += ex2(n3 - m1);
            float A1n = m1 + lg2(s1) + lp1;

            // state 4l+2 (blank): lse2(A2, A1), diff-form
            float m2 = fmaxf(A2, A1);
            float d2 = fabsf(A2 - A1);
            float A2n = m2 + lg2(1.0f + ex2(-d2)) + lpb;

            // state 4l+3 (label): lse3(A3, A2, skip3 ? A1)
            float m3 = fmaxf(A3, A2); if (skip3) m3 = fmaxf(m3, A1);
            float s3 = ex2(A3 - m3) + ex2(A2 - m3);
            if (skip3) s3 += ex2(A1 - m3);
            float A3n = m3 + lg2(s3) + lp3;

            A0 = A0n; A1 = A1n; A2 = A2n; A3 = A3n;
        }
    }

    // ---- loss = -ln2 * lse2(A[96], A[95]) ----
    // state 96 = lane 24 A0 ; state 95 = lane 23 A3
    float a96 = __shfl_sync(0xffffffffu, A0, 24);
    float a95 = __shfl_sync(0xffffffffu, A3, 23);
    if (l == 0) {
        float m = fmaxf(a96, a95);
        float d = fabsf(a96 - a95);
        float r = m + lg2(1.0f + ex2(-d));
        out[b] = -(r * LN2_);
    }
}

extern "C" void kernel_launch(void* const* d_in, const int* in_sizes, int n_in,
                              void* d_out, int out_size)
{
    const float* y_pred = (const float*)d_in[0];   // [B, T, C] f32
    const int*   y_true = (const int*)d_in[1];     // [B, L] int32
    float*       out    = (float*)d_out;           // [B, 1] f32

    ctc_loss_kernel<<<B_, 32>>>(y_pred, y_true, out);
}

// round 8
// speedup vs baseline: 1.6147x; 1.5311x over previous
#include <cuda_runtime.h>

// CTC batch cost — single-warp, LINEAR-domain recursion with block-floating-
// point rescaling. B=128, T=512, C=1024, L=48 -> S=97, blank=1023.
//
// R7 post-mortem: log-domain costs ~15 MUFU warp-ops/step (rt=8/SMSP) with
// serial EX2->LG2 16-cyc chains -> ~285 cyc/step regardless of barrier
// removal. Fix: linear domain. Per step only FADD/FFMA/FMUL + 1 shfl:
//   A0'=(A0+n3)pb; A1'=(A1+A0+skip1*n3)p1; A2'=(A2+A1)pb; A3'=(A3+A2+skip3*A1)p3
// Underflow: common block exponent. Every 4 steps: warp-max -> exponent ->
// scale all alphas to ~2^100 (two-multiply split keeps factors in f32 range),
// accumulate shift in E. The butterfly result is applied one window later
// (stale-by-4) so its 5x26cyc shfl chain interleaves with step work; any
// common scale is correct. Decay bounds (p in [2^-19, 2^-7.4]) keep the max
// in [2^-92, 2^93]: no overflow, max never denormal; states >2^-57 below max
// truncate -- contributing <2^-57 to the final sum (tolerance 1e-3).
//
// y_true is int32 (JAX x64 disabled).

#define B_ 128
#define T_ 512
#define C_ 1024
#define L_ 48
#define BLANK_ (C_ - 1)
#define EPS_ 1e-7f
#define LN2_ 0.6931471805599453f
#define PD_ 12      // prefetch depth = 3 rescale windows
#define TGT_ 100    // target block exponent after rescale

__global__ __launch_bounds__(32, 1)
void ctc_loss_kernel(const float* __restrict__ y_pred,
                     const int* __restrict__ y_true,
                     float* __restrict__ out)
{
    const int b = blockIdx.x;
    const int l = threadIdx.x;      // lane 0..31; lanes 25..31 are dummies

    // ---- per-lane labels + skip flags (state 4l+1 -> label 2l, 4l+3 -> 2l+1)
    int k1 = min(2 * l,     L_ - 1);
    int k3 = min(2 * l + 1, L_ - 1);
    const int* lab = y_true + b * L_;
    const int cls1 = lab[k1];
    const int cls3 = lab[k3];
    const float skip1f = (l == 0) ? 1.0f : (cls1 != lab[k1 - 1] ? 1.0f : 0.0f);
    const float skip3f = (cls3 != cls1) ? 1.0f : 0.0f;

    const float* base = y_pred + (size_t)b * T_ * C_;
    const float* qb = base + BLANK_;   // broadcast across warp
    const float* q1 = base + cls1;
    const float* q3 = base + cls3;

    // ---- t = 0 init (linear domain; zeros = true -inf) ----
    float A0 = 0.0f, A1 = 0.0f, A2 = 0.0f, A3 = 0.0f;
    if (l == 0) { A0 = qb[0] + EPS_; A1 = q1[0] + EPS_; }

    // ---- prefetch ring: raw probs for t = 1..PD_ ----
    float pfb[PD_], pf1[PD_], pf3[PD_];
#pragma unroll
    for (int k = 0; k < PD_; ++k) {
        int t = min(1 + k, T_ - 1);
        size_t o = (size_t)t * C_;
        pfb[k] = qb[o]; pf1[k] = q1[o]; pf3[k] = q3[o];
    }

    float E = 0.0f;     // applied scale: true log2(alpha) = log2(A) + E
    int pending_e;      // block exponent measured last boundary (warp-uniform)
    {
        float m = fmaxf(fmaxf(A0, A1), fmaxf(A2, A3));
#pragma unroll
        for (int d = 16; d; d >>= 1)
            m = fmaxf(m, __shfl_xor_sync(0xffffffffu, m, d));
        pending_e = ((__float_as_int(m) >> 23) & 0xFF) - 127;
    }

    // ---- main: 42 superblocks x 12 steps -> t = 1..504 ----
    for (int sb = 0; sb < 42; ++sb) {
        const int tb = 1 + sb * 12;
#pragma unroll
        for (int u = 0; u < 12; ++u) {
            if ((u & 3) == 0) {
                // apply pending scale (two multiplies: k can exceed 127)
                int k  = TGT_ - pending_e;
                int ka = k >> 1, kb = k - ka;
                float fa = __int_as_float((ka + 127) << 23);
                float fb = __int_as_float((kb + 127) << 23);
                A0 *= fa; A1 *= fa; A2 *= fa; A3 *= fa;
                A0 *= fb; A1 *= fb; A2 *= fb; A3 *= fb;
                E -= (float)k;
                // kick off next (stale) measurement; chain overlaps steps
                float m = fmaxf(fmaxf(A0, A1), fmaxf(A2, A3));
#pragma unroll
                for (int d = 16; d; d >>= 1)
                    m = fmaxf(m, __shfl_xor_sync(0xffffffffu, m, d));
                pending_e = ((__float_as_int(m) >> 23) & 0xFF) - 127;
            }

            const int t = tb + u;
            float pb = pfb[u] + EPS_;
            float p1 = pf1[u] + EPS_;
            float p3 = pf3[u] + EPS_;

            // re-issue loads PD_ steps ahead (clamped at tail)
            int tn = min(t + PD_, T_ - 1);
            size_t o = (size_t)tn * C_;
            pfb[u] = qb[o]; pf1[u] = q1[o]; pf3[u] = q3[o];

            float n3 = __shfl_up_sync(0xffffffffu, A3, 1);
            if (l == 0) n3 = 0.0f;

            float A0n = (A0 + n3) * pb;
            float A1n = fmaf(skip1f, n3, A1 + A0) * p1;
            float A2n = (A2 + A1) * pb;
            float A3n = fmaf(skip3f, A1, A3 + A2) * p3;
            A0 = A0n; A1 = A1n; A2 = A2n; A3 = A3n;
        }
    }

    // ---- tail: t = 505..511 (ring slots j = 0..6 already hold them) ----
#pragma unroll
    for (int j = 0; j < 7; ++j) {
        if ((j & 3) == 0) {
            int k  = TGT_ - pending_e;
            int ka = k >> 1, kb = k - ka;
            float fa = __int_as_float((ka + 127) << 23);
            float fb = __int_as_float((kb + 127) << 23);
            A0 *= fa; A1 *= fa; A2 *= fa; A3 *= fa;
            A0 *= fb; A1 *= fb; A2 *= fb; A3 *= fb;
            E -= (float)k;
            float m = fmaxf(fmaxf(A0, A1), fmaxf(A2, A3));
#pragma unroll
            for (int d = 16; d; d >>= 1)
                m = fmaxf(m, __shfl_xor_sync(0xffffffffu, m, d));
            pending_e = ((__float_as_int(m) >> 23) & 0xFF) - 127;
        }
        float pb = pfb[j] + EPS_;
        float p1 = pf1[j] + EPS_;
        float p3 = pf3[j] + EPS_;
        float n3 = __shfl_up_sync(0xffffffffu, A3, 1);
        if (l == 0) n3 = 0.0f;
        float A0n = (A0 + n3) * pb;
        float A1n = fmaf(skip1f, n3, A1 + A0) * p1;
        float A2n = (A2 + A1) * pb;
        float A3n = fmaf(skip3f, A1, A3 + A2) * p3;
        A0 = A0n; A1 = A1n; A2 = A2n; A3 = A3n;
    }

    // ---- loss = -ln2 * (log2(a96 + a95) + E) ----
    // state 96 = lane 24 A0 ; state 95 = lane 23 A3 (common scale E)
    float a96 = __shfl_sync(0xffffffffu, A0, 24);
    float a95 = __shfl_sync(0xffffffffu, A3, 23);
    if (l == 0) {
        out[b] = -((log2f(a96 + a95) + E) * LN2_);
    }
}

extern "C" void kernel_launch(void* const* d_in, const int* in_sizes, int n_in,
                              void* d_out, int out_size)
{
    const float* y_pred = (const float*)d_in[0];   // [B, T, C] f32
    const int*   y_true = (const int*)d_in[1];     // [B, L] int32
    float*       out    = (float*)d_out;           // [B, 1] f32

    ctc_loss_kernel<<<B_, 32>>>(y_pred, y_true, out);
}